// round 6
// baseline (speedup 1.0000x reference)
#include <cuda_runtime.h>
#include <stdint.h>

#define NN 100000
#define EE 3200000
#define TT 8
#define FF 64
#define CAP 524288            // fixed-stride bucket capacity (>= ~400k + margin)

// ---------------- device scratch (allocation-free) ----------------
__device__ float g_ybuf0[(size_t)NN * FF];    // 25.6 MB slice buffer (parity 0)
__device__ float g_ybuf1[(size_t)NN * FF];    // 25.6 MB slice buffer (parity 1)
__device__ float g_hacc[(size_t)NN * FF];     // 25.6 MB, zero-init, kept zeroed
__device__ float g_h1[(size_t)NN * FF];       // 25.6 MB
__device__ int2  g_edge[(size_t)TT * CAP];    // 32 MB, {src,dst} per t-bucket
__device__ int   g_tcnt[TT];
__device__ int   g_mode;                      // 1 = int64 indices, 0 = int32

#define FMA2(acc, a, b) asm("fma.rn.f32x2 %0, %1, %2, %0;" : "+l"(acc) : "l"(a), "l"(b))
__device__ __forceinline__ unsigned long long dup2(float v) {
    unsigned long long r;
    unsigned int b = __float_as_uint(v);
    asm("mov.b64 %0, {%1, %1};" : "=l"(r) : "r"(b));
    return r;
}
__device__ __forceinline__ unsigned long long pack2(float lo, float hi) {
    unsigned long long r;
    asm("mov.b64 %0, {%1, %2};" : "=l"(r) : "r"(__float_as_uint(lo)), "r"(__float_as_uint(hi)));
    return r;
}

// ---------------- dtype detection ----------------
__global__ void k_detect(const int* __restrict__ ei) {
    __shared__ int any_nonzero;
    if (threadIdx.x == 0) any_nonzero = 0;
    __syncthreads();
    int v = ei[2 * threadIdx.x + 1];
    if (v != 0) atomicExch(&any_nonzero, 1);
    __syncthreads();
    if (threadIdx.x == 0) g_mode = (any_nonzero == 0) ? 1 : 0;
}

__global__ void k_zero_t(void) {
    if (threadIdx.x < TT) g_tcnt[threadIdx.x] = 0;
}

// ---------------- partition edges into fixed-stride t-buckets ----------------
__global__ void k_partition(const void* __restrict__ ei_raw,
                            const void* __restrict__ ti_raw) {
    __shared__ int scnt[TT];
    __shared__ int sbase[TT];
    int tid = threadIdx.x;
    if (tid < TT) scnt[tid] = 0;
    __syncthreads();

    int e = blockIdx.x * 256 + tid;
    int src, dst, t;
    if (g_mode) {
        const long long* ei = (const long long*)ei_raw;
        const long long* ti = (const long long*)ti_raw;
        src = (int)ei[e];
        dst = (int)ei[(size_t)EE + e];
        t   = (int)ti[e];
    } else {
        const int* ei = (const int*)ei_raw;
        const int* ti = (const int*)ti_raw;
        src = ei[e];
        dst = ei[EE + e];
        t   = ti[e];
    }
    int pos = atomicAdd(&scnt[t], 1);
    __syncthreads();
    if (tid < TT) sbase[tid] = atomicAdd(&g_tcnt[tid], scnt[tid]);
    __syncthreads();
    g_edge[(size_t)t * CAP + sbase[t] + pos] = make_int2(src, dst);
}

// ---------------- y_t[n][:] = in[n][:] @ W_t  (one t-slice) ----------------
// block 128 thr, 32 nodes: grp = tid>>3 (2 nodes), cA = tid&7 (cols cA, cA+8)
__global__ void __launch_bounds__(128) k_gemm_t(const float* __restrict__ in,
                                                const float* __restrict__ Wt,
                                                float* __restrict__ ybuf) {
    __shared__ float xs[32 * 68];
    int tid = threadIdx.x;
    int nb  = blockIdx.x * 32;

    const float4* in4 = (const float4*)in + (size_t)nb * 16;
#pragma unroll
    for (int k = 0; k < 4; k++) {
        int i = tid + k * 128;           // 0..511
        int row = i >> 4, c4 = i & 15;
        *(float4*)&xs[row * 68 + c4 * 4] = __ldg(&in4[i]);
    }
    __syncthreads();

    int cA  = tid & 7;
    int grp = tid >> 3;
    int n0  = grp * 2;

    unsigned long long aA0 = 0, aA1 = 0, aB0 = 0, aB1 = 0;
    unsigned long long bA0 = 0, bA1 = 0, bB0 = 0, bB1 = 0;
    const float4* W4 = (const float4*)Wt;   // [64][16]

#pragma unroll 16
    for (int fin = 0; fin < 64; ++fin) {
        float4 wA = __ldg(&W4[fin * 16 + cA]);
        float4 wB = __ldg(&W4[fin * 16 + cA + 8]);
        unsigned long long wA0 = pack2(wA.x, wA.y), wA1 = pack2(wA.z, wA.w);
        unsigned long long wB0 = pack2(wB.x, wB.y), wB1 = pack2(wB.z, wB.w);
        unsigned long long d0 = dup2(xs[n0 * 68 + fin]);
        unsigned long long d1 = dup2(xs[(n0 + 1) * 68 + fin]);
        FMA2(aA0, d0, wA0); FMA2(aA1, d0, wA1);
        FMA2(aB0, d0, wB0); FMA2(aB1, d0, wB1);
        FMA2(bA0, d1, wA0); FMA2(bA1, d1, wA1);
        FMA2(bB0, d1, wB0); FMA2(bB1, d1, wB1);
    }

    ulonglong2* yb = (ulonglong2*)ybuf;
    ulonglong2 o;
    o.x = aA0; o.y = aA1; yb[(size_t)(nb + n0) * 16 + cA]         = o;
    o.x = aB0; o.y = aB1; yb[(size_t)(nb + n0) * 16 + cA + 8]     = o;
    o.x = bA0; o.y = bA1; yb[(size_t)(nb + n0 + 1) * 16 + cA]     = o;
    o.x = bB0; o.y = bB1; yb[(size_t)(nb + n0 + 1) * 16 + cA + 8] = o;
}

// ---------------- scatter one t-bucket: hacc[dst] += y_t[src] ----------------
__global__ void __launch_bounds__(256) k_scatter_t(int t, const float* __restrict__ ybuf) {
    int cnt = __ldg((const int*)&g_tcnt[t]);
    size_t total = (size_t)cnt * 16;
    const int2* eb = &g_edge[(size_t)t * CAP];
    const float4* yb = (const float4*)ybuf;
    float4* hv = (float4*)g_hacc;
    for (size_t idx = (size_t)blockIdx.x * 256 + threadIdx.x; idx < total;
         idx += (size_t)gridDim.x * 256) {
        int e = (int)(idx >> 4);
        int c = (int)(idx & 15);
        int2 ed = __ldg(&eb[e]);
        float4 v = __ldg(&yb[(size_t)ed.x * 16 + c]);
        atomicAdd(&hv[(size_t)ed.y * 16 + c], v);
    }
}

// ---------------- epilogue: out = relu(hacc + b); hacc = 0 ----------------
__global__ void __launch_bounds__(256) k_bias_relu_reset(const float* __restrict__ bias,
                                                         float* __restrict__ out) {
    int i = blockIdx.x * 256 + threadIdx.x;   // < N*16
    float4* hv = (float4*)g_hacc;
    float4 v = hv[i];
    hv[i] = make_float4(0.f, 0.f, 0.f, 0.f);
    float4 b = __ldg(&((const float4*)bias)[i & 15]);
    float4 r;
    r.x = fmaxf(v.x + b.x, 0.f);
    r.y = fmaxf(v.y + b.y, 0.f);
    r.z = fmaxf(v.z + b.z, 0.f);
    r.w = fmaxf(v.w + b.w, 0.f);
    ((float4*)out)[i] = r;
}

// ---------------- ssl = h2 @ Wssl + bssl ----------------
__global__ void __launch_bounds__(256) k_ssl(const float* __restrict__ h2,
                                             const float* __restrict__ Wssl,
                                             const float* __restrict__ bssl,
                                             float* __restrict__ out) {
    __shared__ float ws[64 * 64];
    __shared__ float hs[4 * 64];
    int tid = threadIdx.x;
    int nb  = blockIdx.x * 4;

    {
        float4* wsv = (float4*)ws;
        const float4* Wv = (const float4*)Wssl;
#pragma unroll
        for (int k = 0; k < 4; k++) wsv[tid + k * 256] = Wv[tid + k * 256];
        hs[tid] = h2[(size_t)nb * 64 + tid];
    }
    __syncthreads();

    int nl = tid >> 6;
    int fo = tid & 63;
    float a = __ldg(&bssl[fo]);
#pragma unroll 8
    for (int fin = 0; fin < 64; ++fin)
        a += hs[nl * 64 + fin] * ws[fin * 64 + fo];
    out[(size_t)(nb + nl) * 64 + fo] = a;
}

// ---------------- launch: two-stream t-sliced pipeline ----------------
extern "C" void kernel_launch(void* const* d_in, const int* in_sizes, int n_in,
                              void* d_out, int out_size) {
    const float* x    = (const float*)d_in[0];
    const void*  ei   = d_in[1];
    const void*  ti   = d_in[2];
    const float* W1   = (const float*)d_in[3];
    const float* b1   = (const float*)d_in[4];
    const float* W2   = (const float*)d_in[5];
    const float* b2   = (const float*)d_in[6];
    const float* Wssl = (const float*)d_in[7];
    const float* bssl = (const float*)d_in[8];
    float* out_h   = (float*)d_out;
    float* out_ssl = (float*)d_out + (size_t)NN * 64;

    float* dyb[2];
    cudaGetSymbolAddress((void**)&dyb[0], g_ybuf0);
    cudaGetSymbolAddress((void**)&dyb[1], g_ybuf1);
    float* dh1;  cudaGetSymbolAddress((void**)&dh1, g_h1);

    // one-time host-side resources (created on the uncaptured correctness call)
    static cudaStream_t sA = 0;
    static cudaEvent_t evFork, evJoin, evE1;
    static cudaEvent_t evG[2][8], evS[2][8];
    static int inited = 0;
    if (!inited) {
        cudaStreamCreateWithFlags(&sA, cudaStreamNonBlocking);
        cudaEventCreateWithFlags(&evFork, cudaEventDisableTiming);
        cudaEventCreateWithFlags(&evJoin, cudaEventDisableTiming);
        cudaEventCreateWithFlags(&evE1, cudaEventDisableTiming);
        for (int l = 0; l < 2; l++)
            for (int t = 0; t < 8; t++) {
                cudaEventCreateWithFlags(&evG[l][t], cudaEventDisableTiming);
                cudaEventCreateWithFlags(&evS[l][t], cudaEventDisableTiming);
            }
        inited = 1;
    }

    // fork sA from the capture-origin (legacy) stream
    cudaEventRecord(evFork, 0);
    cudaStreamWaitEvent(sA, evFork, 0);

    // partition edges by t (main stream)
    k_detect<<<1, 256>>>((const int*)ei);
    k_zero_t<<<1, 32>>>();
    k_partition<<<EE / 256, 256>>>(ei, ti);

    const float* lin[2]  = { x, dh1 };
    const float* lW[2]   = { W1, W2 };
    const float* lb[2]   = { b1, b2 };
    float*       lout[2] = { dh1, out_h };

    for (int l = 0; l < 2; l++) {
        for (int t = 0; t < 8; t++) {
            if (t >= 2) cudaStreamWaitEvent(sA, evS[l][t - 2], 0);
            k_gemm_t<<<NN / 32, 128, 0, sA>>>(lin[l], lW[l] + t * 4096, dyb[t & 1]);
            cudaEventRecord(evG[l][t], sA);
            cudaStreamWaitEvent(0, evG[l][t], 0);
            k_scatter_t<<<25000, 256>>>(t, dyb[t & 1]);
            if (t < 6) cudaEventRecord(evS[l][t], 0);
        }
        k_bias_relu_reset<<<(NN * 16) / 256, 256>>>(lb[l], lout[l]);
        if (l == 0) {
            cudaEventRecord(evE1, 0);
            cudaStreamWaitEvent(sA, evE1, 0);
        }
    }

    // join sA back into the origin stream
    cudaEventRecord(evJoin, sA);
    cudaStreamWaitEvent(0, evJoin, 0);

    // ssl head
    k_ssl<<<NN / 4, 256>>>(out_h, Wssl, bssl, out_ssl);
}

// round 7
// speedup vs baseline: 1.0468x; 1.0468x over previous
#include <cuda_runtime.h>
#include <stdint.h>

#define NN 100000
#define EE 3200000
#define TT 8
#define FF 64
#define NB 782                 // ceil(N/128) src blocks
#define NK (NB * TT)           // 6256 sort buckets

// ---------------- device scratch (allocation-free) ----------------
__device__ float g_y[(size_t)TT * NN * FF];   // 204.8 MB: y[t*N+n][f]
__device__ float g_hacc[(size_t)NN * FF];     // 25.6 MB, zero-init, kept zeroed
__device__ float g_h1[(size_t)NN * FF];       // 25.6 MB
__device__ float g_V1[64 * 512];              // permuted W1: V[fin][t*64+fout]
__device__ float g_V2[64 * 512];
__device__ int2  g_sedge[EE];                 // {t*N+src, dst}, sorted by gather key
__device__ int   g_kcnt[NK];
__device__ int   g_kcur[NK];
__device__ int   g_mode;                      // 1 = int64 indices, 0 = int32

#define FMA2(acc, a, b) asm("fma.rn.f32x2 %0, %1, %2, %0;" : "+l"(acc) : "l"(a), "l"(b))

// ---------------- dtype detection ----------------
__global__ void k_detect(const int* __restrict__ ei) {
    __shared__ int any_nonzero;
    if (threadIdx.x == 0) any_nonzero = 0;
    __syncthreads();
    int v = ei[2 * threadIdx.x + 1];
    if (v != 0) atomicExch(&any_nonzero, 1);
    __syncthreads();
    if (threadIdx.x == 0) g_mode = (any_nonzero == 0) ? 1 : 0;
}

__global__ void k_zero_k(void) {
    int i = blockIdx.x * 256 + threadIdx.x;
    if (i < NK) g_kcnt[i] = 0;
}

__device__ __forceinline__ void decode_edge(const void* ei_raw, const void* ti_raw,
                                            int e, int& src, int& dst, int& t) {
    if (g_mode) {
        const long long* ei = (const long long*)ei_raw;
        const long long* ti = (const long long*)ti_raw;
        src = (int)ei[e];
        dst = (int)ei[(size_t)EE + e];
        t   = (int)ti[e];
    } else {
        const int* ei = (const int*)ei_raw;
        const int* ti = (const int*)ti_raw;
        src = ei[e];
        dst = ei[EE + e];
        t   = ti[e];
    }
}

// ---------------- histogram over gather key ----------------
__global__ void k_hist(const void* __restrict__ ei_raw, const void* __restrict__ ti_raw) {
    int e = blockIdx.x * 256 + threadIdx.x;
    if (e >= EE) return;
    int src, dst, t;
    decode_edge(ei_raw, ti_raw, e, src, dst, t);
    int key = (src >> 7) * TT + t;
    atomicAdd(&g_kcnt[key], 1);
}

// ---------------- single-block scan of 6256 counters (7/thread) ----------
__global__ void __launch_bounds__(1024) k_scan(void) {
    __shared__ int ps[1024];
    const int CH = 7;                 // 1024*7 = 7168 >= NK
    int tid = threadIdx.x;
    int base = tid * CH;
    int s = 0;
#pragma unroll
    for (int i = 0; i < CH; i++) {
        int idx = base + i;
        if (idx < NK) s += g_kcnt[idx];
    }
    ps[tid] = s;
    __syncthreads();
    for (int off = 1; off < 1024; off <<= 1) {
        int v = 0;
        if (tid >= off) v = ps[tid - off];
        __syncthreads();
        if (tid >= off) ps[tid] += v;
        __syncthreads();
    }
    int run = (tid == 0) ? 0 : ps[tid - 1];
#pragma unroll
    for (int i = 0; i < CH; i++) {
        int idx = base + i;
        if (idx < NK) {
            g_kcur[idx] = run;
            run += g_kcnt[idx];
        }
    }
}

// ---------------- permute edges into gather-sorted order ----------------
__global__ void k_permute(const void* __restrict__ ei_raw, const void* __restrict__ ti_raw) {
    int e = blockIdx.x * 256 + threadIdx.x;
    if (e >= EE) return;
    int src, dst, t;
    decode_edge(ei_raw, ti_raw, e, src, dst, t);
    int key = (src >> 7) * TT + t;
    int pos = atomicAdd(&g_kcur[key], 1);
    g_sedge[pos] = make_int2(t * NN + src, dst);
}

// ---------------- weight permute: V[fin*512 + t*64+fo] ----------------
__global__ void k_prep_w(const float* __restrict__ W, float* __restrict__ V) {
    int idx = blockIdx.x * blockDim.x + threadIdx.x;   // < 32768
    int fin = idx >> 9;
    int j   = idx & 511;
    int t   = j >> 6;
    int fo  = j & 63;
    V[idx] = W[((t << 6) + fin) * 64 + fo];
}

// ---------------- y[t*N+n][:] = in[n][:] @ W_t  (f32x2 packed FMA) ----------
__global__ void __launch_bounds__(128) k_gemm(const float* __restrict__ in,
                                              const float* __restrict__ V,
                                              float* __restrict__ y) {
    __shared__ float xs[16][64];
    int tid = threadIdx.x;
    int nb  = blockIdx.x * 16;

    {
        const float4* inv = (const float4*)(in + (size_t)nb * 64);
        float4* xsv = (float4*)&xs[0][0];
        xsv[tid]       = inv[tid];
        xsv[tid + 128] = inv[tid + 128];
    }
    __syncthreads();

    int jt = tid & 31;
    int ng = tid >> 5;

    unsigned long long acc[4][4][2];
#pragma unroll
    for (int i = 0; i < 4; i++)
#pragma unroll
        for (int s = 0; s < 4; s++) { acc[i][s][0] = 0ull; acc[i][s][1] = 0ull; }

    const ulonglong2* Vr = (const ulonglong2*)V;

#pragma unroll 4
    for (int fin = 0; fin < 64; ++fin) {
        unsigned long long xv[4];
#pragma unroll
        for (int i = 0; i < 4; i++) {
            unsigned int xb = __float_as_uint(xs[(ng << 2) + i][fin]);
            asm("mov.b64 %0, {%1, %1};" : "=l"(xv[i]) : "r"(xb));
        }
#pragma unroll
        for (int s = 0; s < 4; s++) {
            ulonglong2 w = __ldg(&Vr[fin * 128 + jt + s * 32]);
#pragma unroll
            for (int i = 0; i < 4; i++) {
                FMA2(acc[i][s][0], xv[i], w.x);
                FMA2(acc[i][s][1], xv[i], w.y);
            }
        }
    }

    ulonglong2* yv = (ulonglong2*)y;
#pragma unroll
    for (int s = 0; s < 4; s++) {
        int j4 = jt + s * 32;
        int t  = j4 >> 4;
        int c4 = j4 & 15;
#pragma unroll
        for (int i = 0; i < 4; i++) {
            int node = nb + (ng << 2) + i;
            ulonglong2 o;
            o.x = acc[i][s][0];
            o.y = acc[i][s][1];
            yv[(size_t)(t * NN + node) * 16 + c4] = o;
        }
    }
}

// ---------------- scatter: hacc[dst] += y[gidx]  (sorted gathers) --------
__global__ void __launch_bounds__(256) k_scatter(void) {
    size_t idx = (size_t)blockIdx.x * 256 + threadIdx.x;   // < E*16
    int e = (int)(idx >> 4);
    int c = (int)(idx & 15);
    int2 ed = __ldg(&g_sedge[e]);
    const float4* yv = (const float4*)g_y;
    float4 v = __ldg(&yv[(size_t)ed.x * 16 + c]);
    float4* hv = (float4*)g_hacc;
    atomicAdd(&hv[(size_t)ed.y * 16 + c], v);
}

// ---------------- epilogue: out = relu(hacc + b); hacc = 0 ----------------
__global__ void __launch_bounds__(256) k_bias_relu_reset(const float* __restrict__ bias,
                                                         float* __restrict__ out) {
    int i = blockIdx.x * 256 + threadIdx.x;   // < N*16
    float4* hv = (float4*)g_hacc;
    float4 v = hv[i];
    hv[i] = make_float4(0.f, 0.f, 0.f, 0.f);
    float4 b = __ldg(&((const float4*)bias)[i & 15]);
    float4 r;
    r.x = fmaxf(v.x + b.x, 0.f);
    r.y = fmaxf(v.y + b.y, 0.f);
    r.z = fmaxf(v.z + b.z, 0.f);
    r.w = fmaxf(v.w + b.w, 0.f);
    ((float4*)out)[i] = r;
}

// ---------------- ssl = h2 @ Wssl + bssl ----------------
__global__ void __launch_bounds__(256) k_ssl(const float* __restrict__ h2,
                                             const float* __restrict__ Wssl,
                                             const float* __restrict__ bssl,
                                             float* __restrict__ out) {
    __shared__ float ws[64 * 64];
    __shared__ float hs[4 * 64];
    int tid = threadIdx.x;
    int nb  = blockIdx.x * 4;

    {
        float4* wsv = (float4*)ws;
        const float4* Wv = (const float4*)Wssl;
#pragma unroll
        for (int k = 0; k < 4; k++) wsv[tid + k * 256] = Wv[tid + k * 256];
        hs[tid] = h2[(size_t)nb * 64 + tid];
    }
    __syncthreads();

    int nl = tid >> 6;
    int fo = tid & 63;
    float a = __ldg(&bssl[fo]);
#pragma unroll 8
    for (int fin = 0; fin < 64; ++fin)
        a += hs[nl * 64 + fin] * ws[fin * 64 + fo];
    out[(size_t)(nb + nl) * 64 + fo] = a;
}

// ---------------- launch ----------------
extern "C" void kernel_launch(void* const* d_in, const int* in_sizes, int n_in,
                              void* d_out, int out_size) {
    const float* x    = (const float*)d_in[0];
    const void*  ei   = d_in[1];
    const void*  ti   = d_in[2];
    const float* W1   = (const float*)d_in[3];
    const float* b1   = (const float*)d_in[4];
    const float* W2   = (const float*)d_in[5];
    const float* b2   = (const float*)d_in[6];
    const float* Wssl = (const float*)d_in[7];
    const float* bssl = (const float*)d_in[8];
    float* out_h   = (float*)d_out;
    float* out_ssl = (float*)d_out + (size_t)NN * 64;

    float* dV1;  cudaGetSymbolAddress((void**)&dV1, g_V1);
    float* dV2;  cudaGetSymbolAddress((void**)&dV2, g_V2);
    float* dy;   cudaGetSymbolAddress((void**)&dy, g_y);
    float* dh1;  cudaGetSymbolAddress((void**)&dh1, g_h1);

    // counting sort of edges by gather key (src-block, t)
    k_detect<<<1, 256>>>((const int*)ei);
    k_zero_k<<<(NK + 255) / 256, 256>>>();
    k_hist<<<EE / 256, 256>>>(ei, ti);
    k_scan<<<1, 1024>>>();
    k_permute<<<EE / 256, 256>>>(ei, ti);

    k_prep_w<<<32768 / 256, 256>>>(W1, dV1);
    k_prep_w<<<32768 / 256, 256>>>(W2, dV2);

    // layer 1
    k_gemm<<<NN / 16, 128>>>(x, dV1, dy);
    k_scatter<<<(EE * 16) / 256, 256>>>();
    k_bias_relu_reset<<<(NN * 16) / 256, 256>>>(b1, dh1);

    // layer 2
    k_gemm<<<NN / 16, 128>>>(dh1, dV2, dy);
    k_scatter<<<(EE * 16) / 256, 256>>>();
    k_bias_relu_reset<<<(NN * 16) / 256, 256>>>(b2, out_h);

    // ssl head
    k_ssl<<<NN / 4, 256>>>(out_h, Wssl, bssl, out_ssl);
}